// round 5
// baseline (speedup 1.0000x reference)
#include <cuda_runtime.h>
#include <cstdint>
#include <cstddef>

namespace {

constexpr int kB  = 4;
constexpr int kH  = 8;
constexpr int kL  = 2048;
constexpr int kR  = 8;
constexpr int kDV = 128;

constexpr int TM = 128;          // rows per CTA
constexpr int KT = 32;           // K-tile
constexpr int NT = 256;          // threads
constexpr int NTILES = kL / KT;  // 64

constexpr int PSTRIDE = 36;      // p row stride: A-frag banks qid*4+tig -> conflict-free
constexpr int VSTRIDE = 136;     // v row stride: B-frag banks tig*8+qid -> conflict-free

typedef unsigned long long ull;

__device__ __forceinline__ ull dup2(float x) {
    ull r; asm("mov.b64 %0, {%1,%1};" : "=l"(r) : "f"(x)); return r;
}
__device__ __forceinline__ void unpack2(ull v, float& lo, float& hi) {
    asm("mov.b64 {%0,%1}, %2;" : "=f"(lo), "=f"(hi) : "l"(v));
}
__device__ __forceinline__ ull fma2(ull a, ull b, ull c) {
    ull d; asm("fma.rn.f32x2 %0, %1, %2, %3;" : "=l"(d) : "l"(a), "l"(b), "l"(c));
    return d;
}
__device__ __forceinline__ uint32_t f2tf32(float x) {
    uint32_t r; asm("cvt.rna.tf32.f32 %0, %1;" : "=r"(r) : "f"(x)); return r;
}
__device__ __forceinline__ void mma_tf32(float d[4], const uint32_t a[4],
                                         uint32_t b0, uint32_t b1) {
    asm volatile(
        "mma.sync.aligned.m16n8k8.row.col.f32.tf32.tf32.f32 "
        "{%0,%1,%2,%3}, {%4,%5,%6,%7}, {%8,%9}, {%0,%1,%2,%3};"
        : "+f"(d[0]), "+f"(d[1]), "+f"(d[2]), "+f"(d[3])
        : "r"(a[0]), "r"(a[1]), "r"(a[2]), "r"(a[3]), "r"(b0), "r"(b1));
}

struct __align__(16) SmemLayout {
    float    a2[kR][kL];           // 64 KB
    uint32_t p[2][TM][PSTRIDE];    // 36.9 KB (tf32 A tiles, double buffered)
    uint32_t v[2][KT][VSTRIDE];    // 34.8 KB (tf32 B tiles, double buffered)
    float    inv[TM];              // 512 B
};
// ~137 KB -> 1 CTA/SM

__global__ void __launch_bounds__(NT, 1)
fra_kernel(const float* __restrict__ gv,
           const float* __restrict__ ga1,
           const float* __restrict__ ga2,
           const int*   __restrict__ gmask,
           float* __restrict__ gout,
           float* __restrict__ gattn)
{
    extern __shared__ char smem_raw[];
    SmemLayout& S = *reinterpret_cast<SmemLayout*>(smem_raw);

    const int h    = blockIdx.x;   // heads fastest: 8 heads share mask tile in L2
    const int tile = blockIdx.y;
    const int b    = blockIdx.z;
    const int bh   = b * kH + h;
    const int i0g  = tile * TM;
    const int t    = threadIdx.x;
    const int w    = t >> 5;
    const int l    = t & 31;

    const float* a2base = ga2 + (size_t)bh * kR * kL;
    const float* a1base = ga1 + ((size_t)bh * kL + i0g) * kR;
    const float* vbase  = gv  + (size_t)bh * kL * kDV;
    const int*   mbase  = gmask + ((size_t)b * kL + i0g) * kL;
    float* attnbase = gattn + ((size_t)bh * kL + i0g) * kL;
    float* outbase  = gout  + ((size_t)bh * kL + i0g) * kDV;

    // ---- load a2 slab into smem ----
    {
        const float4* src = (const float4*)a2base;
        float4* dst = (float4*)&S.a2[0][0];
        #pragma unroll
        for (int k = 0; k < (kR * kL / 4) / NT; ++k)
            dst[t + k * NT] = src[t + k * NT];
    }
    __syncthreads();

    // score-thread mapping (both passes): rows rg*4+i, cols cg*4 within tile
    const int rg = t >> 3;   // 0..31
    const int cg = t & 7;    // 0..7

    // a1 for this thread's 4 rows, pre-packed for f32x2
    ull a1d[4][kR];
    #pragma unroll
    for (int i = 0; i < 4; ++i) {
        const float4* src = (const float4*)(a1base + (size_t)(rg * 4 + i) * kR);
        float4 q0 = src[0], q1 = src[1];
        a1d[i][0] = dup2(q0.x); a1d[i][1] = dup2(q0.y);
        a1d[i][2] = dup2(q0.z); a1d[i][3] = dup2(q0.w);
        a1d[i][4] = dup2(q1.x); a1d[i][5] = dup2(q1.y);
        a1d[i][6] = dup2(q1.z); a1d[i][7] = dup2(q1.w);
    }

    // ================= Pass A: e = mask*exp(s) -> gattn (unnormalized); rowsums =================
    float rs[4] = {0.f, 0.f, 0.f, 0.f};
    for (int jt = 0; jt < NTILES; ++jt) {
        const int j0 = jt * KT;
        ull sac[4][2];
        #pragma unroll
        for (int i = 0; i < 4; ++i) { sac[i][0] = 0ULL; sac[i][1] = 0ULL; }
        #pragma unroll
        for (int r = 0; r < kR; ++r) {
            ulonglong2 q = *(const ulonglong2*)&S.a2[r][j0 + cg * 4];
            #pragma unroll
            for (int i = 0; i < 4; ++i) {
                sac[i][0] = fma2(a1d[i][r], q.x, sac[i][0]);
                sac[i][1] = fma2(a1d[i][r], q.y, sac[i][1]);
            }
        }
        #pragma unroll
        for (int i = 0; i < 4; ++i) {
            const int row = rg * 4 + i;
            int4 m = *(const int4*)(mbase + (size_t)row * kL + j0 + cg * 4);
            float e0, e1, e2, e3;
            unpack2(sac[i][0], e0, e1);
            unpack2(sac[i][1], e2, e3);
            float4 e;
            e.x = m.x ? __expf(e0) : 0.f;
            e.y = m.y ? __expf(e1) : 0.f;
            e.z = m.z ? __expf(e2) : 0.f;
            e.w = m.w ? __expf(e3) : 0.f;
            rs[i] += (e.x + e.y) + (e.z + e.w);
            *(float4*)(attnbase + (size_t)row * kL + j0 + cg * 4) = e;
        }
    }
    // reduce rowsums over the 8 threads (cg) sharing each row group
    #pragma unroll
    for (int i = 0; i < 4; ++i) {
        float r = rs[i];
        r += __shfl_xor_sync(0xffffffffu, r, 1);
        r += __shfl_xor_sync(0xffffffffu, r, 2);
        r += __shfl_xor_sync(0xffffffffu, r, 4);
        if (cg == 0) S.inv[rg * 4 + i] = 1.0f / r;
    }
    __syncthreads();   // inv visible; also orders pass-A STG before pass-B LDG (cta fence)

    float invr[4];
    #pragma unroll
    for (int i = 0; i < 4; ++i) invr[i] = S.inv[rg * 4 + i];

    // ================= Pass B: normalize + rewrite attn; tf32 HMMA PV GEMM =================
    // GEMM warp grid 4x2 (wm x wn); warp tile 32 rows x 64 cols
    const int wm  = w >> 1;
    const int wn  = w & 1;
    const int qid = l >> 2;
    const int tig = l & 3;

    float acc[2][8][4];
    #pragma unroll
    for (int mt = 0; mt < 2; ++mt)
        #pragma unroll
        for (int nt = 0; nt < 8; ++nt)
            #pragma unroll
            for (int e = 0; e < 4; ++e) acc[mt][nt][e] = 0.f;

    for (int jt = 0; jt < NTILES; ++jt) {
        const int buf = jt & 1;
        const int j0  = jt * KT;

        // ---- prefetch v rows (coalesced) ----
        float4 vq[4];
        #pragma unroll
        for (int k = 0; k < 4; ++k)
            vq[k] = *(const float4*)(vbase + (size_t)(j0 + w + 8 * k) * kDV + 4 * l);

        // ---- read back e, normalize, rewrite attn, stage p (tf32) ----
        #pragma unroll
        for (int i = 0; i < 4; ++i) {
            const int row = rg * 4 + i;
            float* ap = attnbase + (size_t)row * kL + j0 + cg * 4;
            float4 e = *(const float4*)ap;
            float4 p;
            p.x = e.x * invr[i];
            p.y = e.y * invr[i];
            p.z = e.z * invr[i];
            p.w = e.w * invr[i];
            *(float4*)ap = p;
            uint4 u;
            u.x = f2tf32(p.x); u.y = f2tf32(p.y);
            u.z = f2tf32(p.z); u.w = f2tf32(p.w);
            *(uint4*)&S.p[buf][row][cg * 4] = u;
        }

        // ---- stage v (tf32, conflict-free B layout) ----
        #pragma unroll
        for (int k = 0; k < 4; ++k) {
            uint4 u;
            u.x = f2tf32(vq[k].x); u.y = f2tf32(vq[k].y);
            u.z = f2tf32(vq[k].z); u.w = f2tf32(vq[k].w);
            *(uint4*)&S.v[buf][w + 8 * k][4 * l] = u;
        }

        __syncthreads();   // buf ready for all warps; prior MMA on buf finished by program order

        // ---- HMMA: D[32*wm.., 64*wn..] += P * V ----
        #pragma unroll
        for (int s = 0; s < 4; ++s) {
            const int k0 = 8 * s + tig;
            uint32_t a[2][4];
            #pragma unroll
            for (int mt = 0; mt < 2; ++mt) {
                const uint32_t* pr = &S.p[buf][32 * wm + 16 * mt][0];
                a[mt][0] = pr[(size_t)qid * PSTRIDE + k0];
                a[mt][1] = pr[(size_t)(qid + 8) * PSTRIDE + k0];
                a[mt][2] = pr[(size_t)qid * PSTRIDE + k0 + 4];
                a[mt][3] = pr[(size_t)(qid + 8) * PSTRIDE + k0 + 4];
            }
            #pragma unroll
            for (int nt = 0; nt < 8; ++nt) {
                const int n = 64 * wn + 8 * nt + qid;
                uint32_t b0 = S.v[buf][8 * s + tig][n];
                uint32_t b1 = S.v[buf][8 * s + 4 + tig][n];
                mma_tf32(acc[0][nt], a[0], b0, b1);
                mma_tf32(acc[1][nt], a[1], b0, b1);
            }
        }
        // no trailing barrier: next iter writes the other buffer
    }

    // ---- epilogue: D fragments -> gout ----
    #pragma unroll
    for (int mt = 0; mt < 2; ++mt) {
        #pragma unroll
        for (int nt = 0; nt < 8; ++nt) {
            const int row = 32 * wm + 16 * mt + qid;
            const int col = 64 * wn + 8 * nt + 2 * tig;
            float2 lo; lo.x = acc[mt][nt][0]; lo.y = acc[mt][nt][1];
            float2 hi; hi.x = acc[mt][nt][2]; hi.y = acc[mt][nt][3];
            *(float2*)(outbase + (size_t)row * kDV + col)       = lo;
            *(float2*)(outbase + (size_t)(row + 8) * kDV + col) = hi;
        }
    }
}

} // namespace

extern "C" void kernel_launch(void* const* d_in, const int* in_sizes, int n_in,
                              void* d_out, int out_size) {
    const float* v    = (const float*)d_in[0];
    const float* a1   = (const float*)d_in[1];
    const float* a2   = (const float*)d_in[2];
    const int*   mask = (const int*)d_in[3];

    float* out  = (float*)d_out;
    float* attn = out + (size_t)kB * kH * kL * kDV;

    const int smem = (int)sizeof(SmemLayout);
    cudaFuncSetAttribute(fra_kernel, cudaFuncAttributeMaxDynamicSharedMemorySize, smem);

    dim3 grid(kH, kL / TM, kB);   // heads fastest -> mask tile L2 reuse across 8 heads
    fra_kernel<<<grid, NT, smem>>>(v, a1, a2, mask, out, attn);
}

// round 6
// speedup vs baseline: 1.3329x; 1.3329x over previous
#include <cuda_runtime.h>
#include <cstdint>
#include <cstddef>

namespace {

constexpr int kB  = 4;
constexpr int kH  = 8;
constexpr int kL  = 2048;
constexpr int kR  = 8;
constexpr int kDV = 128;

constexpr int TM = 128;          // rows per CTA
constexpr int KT = 32;           // K-tile
constexpr int NT = 256;          // threads
constexpr int NTILES = kL / KT;  // 64

constexpr int PSTRIDE = 36;      // p row stride: A-frag banks conflict-free
constexpr int VSTRIDE = 136;     // v row stride: B-frag banks conflict-free

typedef unsigned long long ull;

__device__ __forceinline__ ull dup2(float x) {
    ull r; asm("mov.b64 %0, {%1,%1};" : "=l"(r) : "f"(x)); return r;
}
__device__ __forceinline__ void unpack2(ull v, float& lo, float& hi) {
    asm("mov.b64 {%0,%1}, %2;" : "=f"(lo), "=f"(hi) : "l"(v));
}
__device__ __forceinline__ ull fma2(ull a, ull b, ull c) {
    ull d; asm("fma.rn.f32x2 %0, %1, %2, %3;" : "=l"(d) : "l"(a), "l"(b), "l"(c));
    return d;
}
__device__ __forceinline__ uint32_t f2tf32(float x) {
    uint32_t r; asm("cvt.rna.tf32.f32 %0, %1;" : "=r"(r) : "f"(x)); return r;
}
__device__ __forceinline__ void mma_tf32(float d[4], const uint32_t a[4],
                                         uint32_t b0, uint32_t b1) {
    asm volatile(
        "mma.sync.aligned.m16n8k8.row.col.f32.tf32.tf32.f32 "
        "{%0,%1,%2,%3}, {%4,%5,%6,%7}, {%8,%9}, {%0,%1,%2,%3};"
        : "+f"(d[0]), "+f"(d[1]), "+f"(d[2]), "+f"(d[3])
        : "r"(a[0]), "r"(a[1]), "r"(a[2]), "r"(a[3]), "r"(b0), "r"(b1));
}

struct __align__(16) SmemLayout {
    float    a2[kR][kL];           // 64 KB
    uint32_t p[2][TM][PSTRIDE];    // 36.9 KB (tf32 E tiles, double buffered)
    uint32_t v[2][KT][VSTRIDE];    // 34.8 KB (tf32 B tiles, double buffered)
    float    inv[TM];              // 512 B
};
// ~137 KB -> 1 CTA/SM

__global__ void __launch_bounds__(NT, 1)
fra_kernel(const float* __restrict__ gv,
           const float* __restrict__ ga1,
           const float* __restrict__ ga2,
           const int*   __restrict__ gmask,
           float* __restrict__ gout,
           float* __restrict__ gattn)
{
    extern __shared__ char smem_raw[];
    SmemLayout& S = *reinterpret_cast<SmemLayout*>(smem_raw);

    const int h    = blockIdx.x;   // heads fastest: 8 heads share mask tile in L2
    const int tile = blockIdx.y;
    const int b    = blockIdx.z;
    const int bh   = b * kH + h;
    const int i0g  = tile * TM;
    const int t    = threadIdx.x;
    const int w    = t >> 5;
    const int l    = t & 31;

    const float* a2base = ga2 + (size_t)bh * kR * kL;
    const float* a1base = ga1 + ((size_t)bh * kL + i0g) * kR;
    const float* vbase  = gv  + (size_t)bh * kL * kDV;
    const int*   mbase  = gmask + ((size_t)b * kL + i0g) * kL;
    float* attnbase = gattn + ((size_t)bh * kL + i0g) * kL;
    float* outbase  = gout  + ((size_t)bh * kL + i0g) * kDV;

    // ---- load a2 slab into smem ----
    {
        const float4* src = (const float4*)a2base;
        float4* dst = (float4*)&S.a2[0][0];
        #pragma unroll
        for (int k = 0; k < (kR * kL / 4) / NT; ++k)
            dst[t + k * NT] = src[t + k * NT];
    }
    __syncthreads();

    // score mapping: rows rg*4+i, cols cg*4 within tile (8 cg lanes per row, warp-local)
    const int rg = t >> 3;   // 0..31
    const int cg = t & 7;    // 0..7

    float a1r[4][kR];
    #pragma unroll
    for (int i = 0; i < 4; ++i) {
        const float4* src = (const float4*)(a1base + (size_t)(rg * 4 + i) * kR);
        float4 q0 = src[0], q1 = src[1];
        a1r[i][0] = q0.x; a1r[i][1] = q0.y; a1r[i][2] = q0.z; a1r[i][3] = q0.w;
        a1r[i][4] = q1.x; a1r[i][5] = q1.y; a1r[i][6] = q1.z; a1r[i][7] = q1.w;
    }

    // GEMM warp grid 4x2 (wm x wn); warp tile 32 rows x 64 cols
    const int wm  = w >> 1;
    const int wn  = w & 1;
    const int qid = l >> 2;
    const int tig = l & 3;

    float acc[2][8][4];
    #pragma unroll
    for (int mt = 0; mt < 2; ++mt)
        #pragma unroll
        for (int nt = 0; nt < 8; ++nt)
            #pragma unroll
            for (int e = 0; e < 4; ++e) acc[mt][nt][e] = 0.f;

    float rs[4] = {0.f, 0.f, 0.f, 0.f};   // rowsum accumulators (unnormalized)

    // ================= fused sweep: e = mask*exp(s); attn STG; E@V MMA =================
    for (int jt = 0; jt < NTILES; ++jt) {
        const int buf = jt & 1;
        const int j0  = jt * KT;

        // ---- prefetch v rows + mask (hide LDG latency under score FMA) ----
        float4 vq[4];
        #pragma unroll
        for (int k = 0; k < 4; ++k)
            vq[k] = *(const float4*)(vbase + (size_t)(j0 + w + 8 * k) * kDV + 4 * l);
        int4 mq[4];
        #pragma unroll
        for (int i = 0; i < 4; ++i)
            mq[i] = *(const int4*)(mbase + (size_t)(rg * 4 + i) * kL + j0 + cg * 4);

        // ---- scores: 4 rows x 4 cols (f32x2) ----
        ull sac[4][2];
        #pragma unroll
        for (int i = 0; i < 4; ++i) { sac[i][0] = 0ULL; sac[i][1] = 0ULL; }
        #pragma unroll
        for (int r = 0; r < kR; ++r) {
            ulonglong2 q = *(const ulonglong2*)&S.a2[r][j0 + cg * 4];
            #pragma unroll
            for (int i = 0; i < 4; ++i) {
                ull ad = dup2(a1r[i][r]);
                sac[i][0] = fma2(ad, q.x, sac[i][0]);
                sac[i][1] = fma2(ad, q.y, sac[i][1]);
            }
        }

        // ---- e = mask*exp(s): attn STG (unnormalized), rowsum, p STS (tf32) ----
        #pragma unroll
        for (int i = 0; i < 4; ++i) {
            const int row = rg * 4 + i;
            float e0, e1, e2, e3;
            unpack2(sac[i][0], e0, e1);
            unpack2(sac[i][1], e2, e3);
            float4 e;
            e.x = mq[i].x ? __expf(e0) : 0.f;
            e.y = mq[i].y ? __expf(e1) : 0.f;
            e.z = mq[i].z ? __expf(e2) : 0.f;
            e.w = mq[i].w ? __expf(e3) : 0.f;
            rs[i] += (e.x + e.y) + (e.z + e.w);
            *(float4*)(attnbase + (size_t)row * kL + j0 + cg * 4) = e;
            uint4 u;
            u.x = f2tf32(e.x); u.y = f2tf32(e.y);
            u.z = f2tf32(e.z); u.w = f2tf32(e.w);
            *(uint4*)&S.p[buf][row][cg * 4] = u;
        }

        // ---- stage v (tf32, conflict-free B layout) ----
        #pragma unroll
        for (int k = 0; k < 4; ++k) {
            uint4 u;
            u.x = f2tf32(vq[k].x); u.y = f2tf32(vq[k].y);
            u.z = f2tf32(vq[k].z); u.w = f2tf32(vq[k].w);
            *(uint4*)&S.v[buf][w + 8 * k][4 * l] = u;
        }

        __syncthreads();   // buf ready; prior MMA on this buf done (barrier ordering)

        // ---- HMMA: D[32*wm.., 64*wn..] += E * V ----
        #pragma unroll
        for (int s = 0; s < 4; ++s) {
            const int k0 = 8 * s + tig;
            uint32_t a[2][4];
            #pragma unroll
            for (int mt = 0; mt < 2; ++mt) {
                const uint32_t* pr = &S.p[buf][32 * wm + 16 * mt][0];
                a[mt][0] = pr[(size_t)qid * PSTRIDE + k0];
                a[mt][1] = pr[(size_t)(qid + 8) * PSTRIDE + k0];
                a[mt][2] = pr[(size_t)qid * PSTRIDE + k0 + 4];
                a[mt][3] = pr[(size_t)(qid + 8) * PSTRIDE + k0 + 4];
            }
            #pragma unroll
            for (int nt = 0; nt < 8; ++nt) {
                const int n = 64 * wn + 8 * nt + qid;
                uint32_t b0 = S.v[buf][8 * s + tig][n];
                uint32_t b1 = S.v[buf][8 * s + 4 + tig][n];
                mma_tf32(acc[0][nt], a[0], b0, b1);
                mma_tf32(acc[1][nt], a[1], b0, b1);
            }
        }
        // no trailing barrier: next iter writes the other buffer
    }

    // ---- rowsum reduce over the 8 cg lanes (warp-local) -> invr + smem for GEMM mapping ----
    float invr[4];
    #pragma unroll
    for (int i = 0; i < 4; ++i) {
        float r = rs[i];
        r += __shfl_xor_sync(0xffffffffu, r, 1);
        r += __shfl_xor_sync(0xffffffffu, r, 2);
        r += __shfl_xor_sync(0xffffffffu, r, 4);
        invr[i] = 1.0f / r;
        if (cg == 0) S.inv[rg * 4 + i] = invr[i];
    }
    __syncthreads();

    // ---- out epilogue: scale accumulators by row inv ----
    #pragma unroll
    for (int mt = 0; mt < 2; ++mt) {
        const int row0 = 32 * wm + 16 * mt + qid;
        const float ivlo = S.inv[row0];
        const float ivhi = S.inv[row0 + 8];
        #pragma unroll
        for (int nt = 0; nt < 8; ++nt) {
            const int col = 64 * wn + 8 * nt + 2 * tig;
            float2 lo; lo.x = acc[mt][nt][0] * ivlo; lo.y = acc[mt][nt][1] * ivlo;
            float2 hi; hi.x = acc[mt][nt][2] * ivhi; hi.y = acc[mt][nt][3] * ivhi;
            *(float2*)(outbase + (size_t)row0 * kDV + col)       = lo;
            *(float2*)(outbase + (size_t)(row0 + 8) * kDV + col) = hi;
        }
    }

    // ---- attn rescale: each thread rescales exactly the float4s it wrote ----
    #pragma unroll
    for (int i = 0; i < 4; ++i) {
        float* aprow = attnbase + (size_t)(rg * 4 + i) * kL + cg * 4;
        const float iv = invr[i];
        #pragma unroll 4
        for (int jt = 0; jt < NTILES; ++jt) {
            float4 e = *(const float4*)(aprow + jt * KT);
            e.x *= iv; e.y *= iv; e.z *= iv; e.w *= iv;
            *(float4*)(aprow + jt * KT) = e;
        }
    }
}

} // namespace

extern "C" void kernel_launch(void* const* d_in, const int* in_sizes, int n_in,
                              void* d_out, int out_size) {
    const float* v    = (const float*)d_in[0];
    const float* a1   = (const float*)d_in[1];
    const float* a2   = (const float*)d_in[2];
    const int*   mask = (const int*)d_in[3];

    float* out  = (float*)d_out;
    float* attn = out + (size_t)kB * kH * kL * kDV;

    const int smem = (int)sizeof(SmemLayout);
    cudaFuncSetAttribute(fra_kernel, cudaFuncAttributeMaxDynamicSharedMemorySize, smem);

    dim3 grid(kH, kL / TM, kB);   // heads fastest -> mask tile L2 reuse across 8 heads
    fra_kernel<<<grid, NT, smem>>>(v, a1, a2, mask, out, attn);
}

// round 7
// speedup vs baseline: 1.7372x; 1.3033x over previous
#include <cuda_runtime.h>
#include <cstdint>
#include <cstddef>

namespace {

constexpr int kB  = 4;
constexpr int kH  = 8;
constexpr int kL  = 2048;
constexpr int kR  = 8;
constexpr int kDV = 128;

constexpr int TM = 64;           // rows per CTA
constexpr int KT = 32;           // K-tile
constexpr int NT = 256;          // threads
constexpr int NTILES = kL / KT;  // 64

constexpr int PSTRIDE = 36;      // p row stride (u32): A-frag conflict-free
constexpr int VSTRIDE = 136;     // v row stride (u32): B-frag conflict-free

typedef unsigned long long ull;

__device__ __forceinline__ ull dup2(float x) {
    ull r; asm("mov.b64 %0, {%1,%1};" : "=l"(r) : "f"(x)); return r;
}
__device__ __forceinline__ void unpack2(ull v, float& lo, float& hi) {
    asm("mov.b64 {%0,%1}, %2;" : "=f"(lo), "=f"(hi) : "l"(v));
}
__device__ __forceinline__ ull fma2(ull a, ull b, ull c) {
    ull d; asm("fma.rn.f32x2 %0, %1, %2, %3;" : "=l"(d) : "l"(a), "l"(b), "l"(c));
    return d;
}
__device__ __forceinline__ uint32_t f2tf32(float x) {
    uint32_t r; asm("cvt.rna.tf32.f32 %0, %1;" : "=r"(r) : "f"(x)); return r;
}
__device__ __forceinline__ void mma_tf32(float d[4], const uint32_t a[4],
                                         uint32_t b0, uint32_t b1) {
    asm volatile(
        "mma.sync.aligned.m16n8k8.row.col.f32.tf32.tf32.f32 "
        "{%0,%1,%2,%3}, {%4,%5,%6,%7}, {%8,%9}, {%0,%1,%2,%3};"
        : "+f"(d[0]), "+f"(d[1]), "+f"(d[2]), "+f"(d[3])
        : "r"(a[0]), "r"(a[1]), "r"(a[2]), "r"(a[3]), "r"(b0), "r"(b1));
}

struct __align__(16) SmemLayout {
    uint32_t p[2][TM][PSTRIDE];    // 18.4 KB (tf32 E tiles, double buffered)
    uint32_t v[2][KT][VSTRIDE];    // 34.8 KB (tf32 B tiles, double buffered)
    float    a2t[2][kR][KT];       // 2 KB   (streamed a2 K-tiles)
    float    inv[TM];              // 256 B
};
// ~55.5 KB -> 2 CTAs/SM

__global__ void __launch_bounds__(NT, 2)
fra_kernel(const float* __restrict__ gv,
           const float* __restrict__ ga1,
           const float* __restrict__ ga2,
           const int*   __restrict__ gmask,
           float* __restrict__ gout,
           float* __restrict__ gattn)
{
    extern __shared__ char smem_raw[];
    SmemLayout& S = *reinterpret_cast<SmemLayout*>(smem_raw);

    const int h    = blockIdx.x;   // heads fastest: 8 heads share mask tile in L2
    const int tile = blockIdx.y;
    const int b    = blockIdx.z;
    const int bh   = b * kH + h;
    const int i0g  = tile * TM;
    const int t    = threadIdx.x;
    const int w    = t >> 5;
    const int l    = t & 31;

    const float* a2base = ga2 + (size_t)bh * kR * kL;
    const float* a1base = ga1 + ((size_t)bh * kL + i0g) * kR;
    const float* vbase  = gv  + (size_t)bh * kL * kDV;
    const int*   mbase  = gmask + ((size_t)b * kL + i0g) * kL;
    float* attnbase = gattn + ((size_t)bh * kL + i0g) * kL;
    float* outbase  = gout  + ((size_t)bh * kL + i0g) * kDV;

    // score mapping: rows 2*rp+i (i=0,1), cols cg*4 within K-tile
    const int rp = t >> 3;   // 0..31
    const int cg = t & 7;    // 0..7

    // a1 for this thread's 2 rows
    float a1r[2][kR];
    #pragma unroll
    for (int i = 0; i < 2; ++i) {
        const float4* src = (const float4*)(a1base + (size_t)(rp * 2 + i) * kR);
        float4 q0 = src[0], q1 = src[1];
        a1r[i][0] = q0.x; a1r[i][1] = q0.y; a1r[i][2] = q0.z; a1r[i][3] = q0.w;
        a1r[i][4] = q1.x; a1r[i][5] = q1.y; a1r[i][6] = q1.z; a1r[i][7] = q1.w;
    }

    // GEMM warp grid 2x4 (wm x wn); warp tile 32 rows x 32 cols
    const int wm  = w >> 2;
    const int wn  = w & 3;
    const int qid = l >> 2;
    const int tig = l & 3;

    float acc[2][4][4];
    #pragma unroll
    for (int mt = 0; mt < 2; ++mt)
        #pragma unroll
        for (int nt = 0; nt < 4; ++nt)
            #pragma unroll
            for (int e = 0; e < 4; ++e) acc[mt][nt][e] = 0.f;

    float rs[2] = {0.f, 0.f};

    // ---- prologue: stage a2 tile 0 ----
    const int ar = t >> 3;   // a2 stage row (t<64)
    const int ac = t & 7;    // a2 stage col group
    if (t < 64)
        *(float4*)&S.a2t[0][ar][ac * 4] =
            *(const float4*)(a2base + (size_t)ar * kL + ac * 4);
    __syncthreads();

    // ================= fused sweep: e = mask*exp(s); attn STG; E@V MMA =================
    for (int jt = 0; jt < NTILES; ++jt) {
        const int buf = jt & 1;
        const int j0  = jt * KT;

        // ---- prefetch next a2 tile, v rows, mask (hide LDG under FMA) ----
        float4 a2n;
        const int jn = (jt + 1 < NTILES) ? j0 + KT : 0;
        if (t < 64)
            a2n = *(const float4*)(a2base + (size_t)ar * kL + jn + ac * 4);
        float4 vq[4];
        #pragma unroll
        for (int k = 0; k < 4; ++k)
            vq[k] = *(const float4*)(vbase + (size_t)(j0 + w + 8 * k) * kDV + 4 * l);
        int4 mq[2];
        #pragma unroll
        for (int i = 0; i < 2; ++i)
            mq[i] = *(const int4*)(mbase + (size_t)(rp * 2 + i) * kL + j0 + cg * 4);

        // ---- scores: 2 rows x 4 cols (f32x2) from smem a2 tile ----
        ull sac[2][2];
        sac[0][0] = 0ULL; sac[0][1] = 0ULL;
        sac[1][0] = 0ULL; sac[1][1] = 0ULL;
        #pragma unroll
        for (int r = 0; r < kR; ++r) {
            ulonglong2 q = *(const ulonglong2*)&S.a2t[buf][r][cg * 4];
            #pragma unroll
            for (int i = 0; i < 2; ++i) {
                ull ad = dup2(a1r[i][r]);
                sac[i][0] = fma2(ad, q.x, sac[i][0]);
                sac[i][1] = fma2(ad, q.y, sac[i][1]);
            }
        }

        // ---- e = mask*exp(s): attn STG (unnormalized), rowsum, p STS (tf32) ----
        #pragma unroll
        for (int i = 0; i < 2; ++i) {
            const int row = rp * 2 + i;
            float e0, e1, e2, e3;
            unpack2(sac[i][0], e0, e1);
            unpack2(sac[i][1], e2, e3);
            float4 e;
            e.x = mq[i].x ? __expf(e0) : 0.f;
            e.y = mq[i].y ? __expf(e1) : 0.f;
            e.z = mq[i].z ? __expf(e2) : 0.f;
            e.w = mq[i].w ? __expf(e3) : 0.f;
            rs[i] += (e.x + e.y) + (e.z + e.w);
            *(float4*)(attnbase + (size_t)row * kL + j0 + cg * 4) = e;
            uint4 u;
            u.x = f2tf32(e.x); u.y = f2tf32(e.y);
            u.z = f2tf32(e.z); u.w = f2tf32(e.w);
            *(uint4*)&S.p[buf][row][cg * 4] = u;
        }

        // ---- stage v (tf32, conflict-free B layout) ----
        #pragma unroll
        for (int k = 0; k < 4; ++k) {
            uint4 u;
            u.x = f2tf32(vq[k].x); u.y = f2tf32(vq[k].y);
            u.z = f2tf32(vq[k].z); u.w = f2tf32(vq[k].w);
            *(uint4*)&S.v[buf][w + 8 * k][4 * l] = u;
        }

        // ---- stage next a2 tile into the other buffer ----
        if (t < 64)
            *(float4*)&S.a2t[buf ^ 1][ar][ac * 4] = a2n;

        __syncthreads();   // buf ready; prior MMA on this buf done (barrier ordering)

        // ---- HMMA: D[32*wm.., 32*wn..] += E * V ----
        #pragma unroll
        for (int s = 0; s < 4; ++s) {
            const int k0 = 8 * s + tig;
            uint32_t a[2][4];
            #pragma unroll
            for (int mt = 0; mt < 2; ++mt) {
                const uint32_t* pr = &S.p[buf][32 * wm + 16 * mt][0];
                a[mt][0] = pr[(size_t)qid * PSTRIDE + k0];
                a[mt][1] = pr[(size_t)(qid + 8) * PSTRIDE + k0];
                a[mt][2] = pr[(size_t)qid * PSTRIDE + k0 + 4];
                a[mt][3] = pr[(size_t)(qid + 8) * PSTRIDE + k0 + 4];
            }
            #pragma unroll
            for (int nt = 0; nt < 4; ++nt) {
                const int n = 32 * wn + 8 * nt + qid;
                uint32_t b0 = S.v[buf][8 * s + tig][n];
                uint32_t b1 = S.v[buf][8 * s + 4 + tig][n];
                mma_tf32(acc[0][nt], a[0], b0, b1);
                mma_tf32(acc[1][nt], a[1], b0, b1);
            }
        }
        // no trailing barrier: next iter writes the other buffer
    }

    // ---- rowsum reduce over 8 cg lanes (warp-local) ----
    float invr[2];
    #pragma unroll
    for (int i = 0; i < 2; ++i) {
        float r = rs[i];
        r += __shfl_xor_sync(0xffffffffu, r, 1);
        r += __shfl_xor_sync(0xffffffffu, r, 2);
        r += __shfl_xor_sync(0xffffffffu, r, 4);
        invr[i] = 1.0f / r;
        if (cg == 0) S.inv[rp * 2 + i] = invr[i];
    }
    __syncthreads();

    // ---- out epilogue: scale accumulators by row inv ----
    #pragma unroll
    for (int mt = 0; mt < 2; ++mt) {
        const int row0 = 32 * wm + 16 * mt + qid;
        const float ivlo = S.inv[row0];
        const float ivhi = S.inv[row0 + 8];
        #pragma unroll
        for (int nt = 0; nt < 4; ++nt) {
            const int col = 32 * wn + 8 * nt + 2 * tig;
            float2 lo; lo.x = acc[mt][nt][0] * ivlo; lo.y = acc[mt][nt][1] * ivlo;
            float2 hi; hi.x = acc[mt][nt][2] * ivhi; hi.y = acc[mt][nt][3] * ivhi;
            *(float2*)(outbase + (size_t)row0 * kDV + col)       = lo;
            *(float2*)(outbase + (size_t)(row0 + 8) * kDV + col) = hi;
        }
    }

    // ---- attn rescale: each thread rescales exactly the float4s it wrote ----
    #pragma unroll
    for (int i = 0; i < 2; ++i) {
        float* aprow = attnbase + (size_t)(rp * 2 + i) * kL + cg * 4;
        const float iv = invr[i];
        #pragma unroll 4
        for (int jt = 0; jt < NTILES; ++jt) {
            float4 e = *(const float4*)(aprow + jt * KT);
            e.x *= iv; e.y *= iv; e.z *= iv; e.w *= iv;
            *(float4*)(aprow + jt * KT) = e;
        }
    }
}

} // namespace

extern "C" void kernel_launch(void* const* d_in, const int* in_sizes, int n_in,
                              void* d_out, int out_size) {
    const float* v    = (const float*)d_in[0];
    const float* a1   = (const float*)d_in[1];
    const float* a2   = (const float*)d_in[2];
    const int*   mask = (const int*)d_in[3];

    float* out  = (float*)d_out;
    float* attn = out + (size_t)kB * kH * kL * kDV;

    const int smem = (int)sizeof(SmemLayout);
    cudaFuncSetAttribute(fra_kernel, cudaFuncAttributeMaxDynamicSharedMemorySize, smem);

    dim3 grid(kH, kL / TM, kB);   // heads fastest -> mask tile L2 reuse across 8 heads
    fra_kernel<<<grid, NT, smem>>>(v, a1, a2, mask, out, attn);
}

// round 8
// speedup vs baseline: 2.1054x; 1.2119x over previous
#include <cuda_runtime.h>
#include <cstdint>
#include <cstddef>

namespace {

constexpr int kB  = 4;
constexpr int kH  = 8;
constexpr int kL  = 2048;
constexpr int kR  = 8;
constexpr int kDV = 128;

constexpr int TM = 64;           // rows per CTA
constexpr int KT = 32;           // K-tile
constexpr int NT = 256;          // threads
constexpr int NTILES = kL / KT;  // 64

constexpr int PSTRIDE = 36;      // p row stride (u32): A-frag conflict-free
constexpr int VSTRIDE = 136;     // v row stride (u32): B-frag conflict-free
constexpr float kLog2e = 1.44269504088896340736f;

typedef unsigned long long ull;

__device__ __forceinline__ ull dup2(float x) {
    ull r; asm("mov.b64 %0, {%1,%1};" : "=l"(r) : "f"(x)); return r;
}
__device__ __forceinline__ void unpack2(ull v, float& lo, float& hi) {
    asm("mov.b64 {%0,%1}, %2;" : "=f"(lo), "=f"(hi) : "l"(v));
}
__device__ __forceinline__ ull fma2(ull a, ull b, ull c) {
    ull d; asm("fma.rn.f32x2 %0, %1, %2, %3;" : "=l"(d) : "l"(a), "l"(b), "l"(c));
    return d;
}
__device__ __forceinline__ uint32_t f2tf32(float x) {
    uint32_t r; asm("cvt.rna.tf32.f32 %0, %1;" : "=r"(r) : "f"(x)); return r;
}
__device__ __forceinline__ float ex2(float x) {
    float r; asm("ex2.approx.f32 %0, %1;" : "=f"(r) : "f"(x)); return r;
}
__device__ __forceinline__ void mma_tf32(float d[4], const uint32_t a[4],
                                         uint32_t b0, uint32_t b1) {
    asm volatile(
        "mma.sync.aligned.m16n8k8.row.col.f32.tf32.tf32.f32 "
        "{%0,%1,%2,%3}, {%4,%5,%6,%7}, {%8,%9}, {%0,%1,%2,%3};"
        : "+f"(d[0]), "+f"(d[1]), "+f"(d[2]), "+f"(d[3])
        : "r"(a[0]), "r"(a[1]), "r"(a[2]), "r"(a[3]), "r"(b0), "r"(b1));
}
__device__ __forceinline__ uint32_t smem_u32(const void* p) {
    uint32_t a;
    asm("{ .reg .u64 t; cvta.to.shared.u64 t, %1; cvt.u32.u64 %0, t; }"
        : "=r"(a) : "l"(p));
    return a;
}
__device__ __forceinline__ void cp16(uint32_t saddr, const void* g) {
    asm volatile("cp.async.ca.shared.global [%0], [%1], 16;"
                 :: "r"(saddr), "l"(g) : "memory");
}
__device__ __forceinline__ void cp_commit() {
    asm volatile("cp.async.commit_group;" ::: "memory");
}
__device__ __forceinline__ void cp_wait1() {
    asm volatile("cp.async.wait_group 1;" ::: "memory");
}

struct __align__(16) SmemLayout {
    uint32_t p[2][TM][PSTRIDE];    // 18.4 KB (tf32 E tiles, double buffered)
    uint32_t v[3][KT][VSTRIDE];    // 52.2 KB (raw f32 v tiles, cp.async ring)
    float    a2t[2][kR][KT];       // 2 KB   (streamed a2 K-tiles)
    float    inv[TM];              // 256 B
};
// ~73 KB -> 2 CTAs/SM

__global__ void __launch_bounds__(NT, 2)
fra_kernel(const float* __restrict__ gv,
           const float* __restrict__ ga1,
           const float* __restrict__ ga2,
           const int*   __restrict__ gmask,
           float* __restrict__ gout,
           float* __restrict__ gattn)
{
    extern __shared__ char smem_raw[];
    SmemLayout& S = *reinterpret_cast<SmemLayout*>(smem_raw);

    const int h    = blockIdx.x;   // heads fastest: 8 heads share mask tile in L2
    const int tile = blockIdx.y;
    const int b    = blockIdx.z;
    const int bh   = b * kH + h;
    const int i0g  = tile * TM;
    const int t    = threadIdx.x;
    const int w    = t >> 5;
    const int l    = t & 31;

    const float* a2base = ga2 + (size_t)bh * kR * kL;
    const float* a1base = ga1 + ((size_t)bh * kL + i0g) * kR;
    const float* vbase  = gv  + (size_t)bh * kL * kDV;
    const int*   mbase  = gmask + ((size_t)b * kL + i0g) * kL;
    float* attnbase = gattn + ((size_t)bh * kL + i0g) * kL;
    float* outbase  = gout  + ((size_t)bh * kL + i0g) * kDV;

    // score mapping: rows 2*rp+i (i=0,1), cols cg*4 within K-tile
    const int rp = t >> 3;   // 0..31
    const int cg = t & 7;    // 0..7

    // a1 (pre-scaled by log2e for ex2) for this thread's 2 rows
    float a1r[2][kR];
    #pragma unroll
    for (int i = 0; i < 2; ++i) {
        const float4* src = (const float4*)(a1base + (size_t)(rp * 2 + i) * kR);
        float4 q0 = src[0], q1 = src[1];
        a1r[i][0] = q0.x * kLog2e; a1r[i][1] = q0.y * kLog2e;
        a1r[i][2] = q0.z * kLog2e; a1r[i][3] = q0.w * kLog2e;
        a1r[i][4] = q1.x * kLog2e; a1r[i][5] = q1.y * kLog2e;
        a1r[i][6] = q1.z * kLog2e; a1r[i][7] = q1.w * kLog2e;
    }

    // GEMM warp grid 2x4 (wm x wn); warp tile 32 rows x 32 cols
    const int wm  = w >> 2;
    const int wn  = w & 3;
    const int qid = l >> 2;
    const int tig = l & 3;

    float acc[2][4][4];
    #pragma unroll
    for (int mt = 0; mt < 2; ++mt)
        #pragma unroll
        for (int nt = 0; nt < 4; ++nt)
            #pragma unroll
            for (int e = 0; e < 4; ++e) acc[mt][nt][e] = 0.f;

    float rs[2] = {0.f, 0.f};

    // ---- cp.async v addressing ----
    const uint32_t vs_base = smem_u32(&S.v[0][0][0]);
    uint32_t voff[4];
    #pragma unroll
    for (int k = 0; k < 4; ++k)
        voff[k] = (uint32_t)(((w + 8 * k) * VSTRIDE + 4 * l) * 4);
    const float* vg[4];
    #pragma unroll
    for (int k = 0; k < 4; ++k)
        vg[k] = vbase + (size_t)(w + 8 * k) * kDV + 4 * l;
    constexpr uint32_t VSLOT = KT * VSTRIDE * 4;   // bytes per slot
    constexpr size_t   VGT   = (size_t)KT * kDV;   // global floats per tile

    // ---- prologue ----
    // v tile 0 -> slot 0
    #pragma unroll
    for (int k = 0; k < 4; ++k) cp16(vs_base + voff[k], vg[k]);
    cp_commit();

    // a2 tile 0
    const int ar = t >> 3;
    const int ac = t & 7;
    if (t < 64)
        *(float4*)&S.a2t[0][ar][ac * 4] =
            *(const float4*)(a2base + (size_t)ar * kL + ac * 4);

    // mask tiles 0,1 preloaded (parity buffer)
    int4 mq_buf[2][2];
    #pragma unroll
    for (int i = 0; i < 2; ++i) {
        mq_buf[0][i] = *(const int4*)(mbase + (size_t)(rp * 2 + i) * kL + 0 * KT + cg * 4);
        mq_buf[1][i] = *(const int4*)(mbase + (size_t)(rp * 2 + i) * kL + 1 * KT + cg * 4);
    }
    __syncthreads();

    // ================= fused sweep: e = mask*exp(s); attn STG; E@V MMA =================
    int vcur = 0, vnxt = 1;
    #pragma unroll 2
    for (int jt = 0; jt < NTILES; ++jt) {
        const int buf = jt & 1;
        const int j0  = jt * KT;

        // ---- issue cp.async for v tile jt+1 into slot vnxt ----
        {
            const size_t goff = (jt + 1 < NTILES) ? (size_t)(jt + 1) * VGT : 0;
            const uint32_t sb = vs_base + (uint32_t)vnxt * VSLOT;
            #pragma unroll
            for (int k = 0; k < 4; ++k) cp16(sb + voff[k], vg[k] + goff);
            cp_commit();
        }

        // ---- prefetch next a2 tile ----
        float4 a2n;
        const int jn = (jt + 1 < NTILES) ? j0 + KT : 0;
        if (t < 64)
            a2n = *(const float4*)(a2base + (size_t)ar * kL + jn + ac * 4);

        // ---- scores: 2 rows x 4 cols (f32x2) from smem a2 tile ----
        ull sac[2][2];
        sac[0][0] = 0ULL; sac[0][1] = 0ULL;
        sac[1][0] = 0ULL; sac[1][1] = 0ULL;
        #pragma unroll
        for (int r = 0; r < kR; ++r) {
            ulonglong2 q = *(const ulonglong2*)&S.a2t[buf][r][cg * 4];
            #pragma unroll
            for (int i = 0; i < 2; ++i) {
                ull ad = dup2(a1r[i][r]);
                sac[i][0] = fma2(ad, q.x, sac[i][0]);
                sac[i][1] = fma2(ad, q.y, sac[i][1]);
            }
        }

        // ---- e = mask*exp2(s~): attn STG (unnormalized), rowsum, p STS (tf32) ----
        #pragma unroll
        for (int i = 0; i < 2; ++i) {
            const int row = rp * 2 + i;
            const int4 m = mq_buf[buf][i];
            float e0, e1, e2, e3;
            unpack2(sac[i][0], e0, e1);
            unpack2(sac[i][1], e2, e3);
            float4 e;
            e.x = m.x ? ex2(e0) : 0.f;
            e.y = m.y ? ex2(e1) : 0.f;
            e.z = m.z ? ex2(e2) : 0.f;
            e.w = m.w ? ex2(e3) : 0.f;
            rs[i] += (e.x + e.y) + (e.z + e.w);
            *(float4*)(attnbase + (size_t)row * kL + j0 + cg * 4) = e;
            uint4 u;
            u.x = f2tf32(e.x); u.y = f2tf32(e.y);
            u.z = f2tf32(e.z); u.w = f2tf32(e.w);
            *(uint4*)&S.p[buf][row][cg * 4] = u;
        }

        // ---- mask prefetch 2 tiles ahead (into the parity slot just consumed) ----
        {
            const int jm = (jt + 2 < NTILES) ? (jt + 2) * KT : 0;
            #pragma unroll
            for (int i = 0; i < 2; ++i)
                mq_buf[buf][i] =
                    *(const int4*)(mbase + (size_t)(rp * 2 + i) * kL + jm + cg * 4);
        }

        // ---- stage next a2 tile into the other buffer ----
        if (t < 64)
            *(float4*)&S.a2t[buf ^ 1][ar][ac * 4] = a2n;

        cp_wait1();        // v tile jt resident (group jt done; group jt+1 may fly)
        __syncthreads();   // publish p/a2/v(jt)

        // ---- HMMA: D[32*wm.., 32*wn..] += E * V  (V raw f32 -> tf32 truncation) ----
        const uint32_t* vt = &S.v[vcur][0][0];
        #pragma unroll
        for (int s = 0; s < 4; ++s) {
            const int k0 = 8 * s + tig;
            uint32_t a[2][4];
            #pragma unroll
            for (int mt = 0; mt < 2; ++mt) {
                const uint32_t* pr = &S.p[buf][32 * wm + 16 * mt][0];
                a[mt][0] = pr[(size_t)qid * PSTRIDE + k0];
                a[mt][1] = pr[(size_t)(qid + 8) * PSTRIDE + k0];
                a[mt][2] = pr[(size_t)qid * PSTRIDE + k0 + 4];
                a[mt][3] = pr[(size_t)(qid + 8) * PSTRIDE + k0 + 4];
            }
            #pragma unroll
            for (int nt = 0; nt < 4; ++nt) {
                const int n = 32 * wn + 8 * nt + qid;
                uint32_t b0 = vt[(size_t)(8 * s + tig) * VSTRIDE + n];
                uint32_t b1 = vt[(size_t)(8 * s + 4 + tig) * VSTRIDE + n];
                mma_tf32(acc[0][nt], a[0], b0, b1);
                mma_tf32(acc[1][nt], a[1], b0, b1);
            }
        }

        vcur = vnxt;
        vnxt = (vnxt == 2) ? 0 : vnxt + 1;
    }

    // ---- rowsum reduce over 8 cg lanes (warp-local) ----
    float invr[2];
    #pragma unroll
    for (int i = 0; i < 2; ++i) {
        float r = rs[i];
        r += __shfl_xor_sync(0xffffffffu, r, 1);
        r += __shfl_xor_sync(0xffffffffu, r, 2);
        r += __shfl_xor_sync(0xffffffffu, r, 4);
        invr[i] = 1.0f / r;
        if (cg == 0) S.inv[rp * 2 + i] = invr[i];
    }
    __syncthreads();

    // ---- out epilogue: scale accumulators by row inv ----
    #pragma unroll
    for (int mt = 0; mt < 2; ++mt) {
        const int row0 = 32 * wm + 16 * mt + qid;
        const float ivlo = S.inv[row0];
        const float ivhi = S.inv[row0 + 8];
        #pragma unroll
        for (int nt = 0; nt < 4; ++nt) {
            const int col = 32 * wn + 8 * nt + 2 * tig;
            float2 lo; lo.x = acc[mt][nt][0] * ivlo; lo.y = acc[mt][nt][1] * ivlo;
            float2 hi; hi.x = acc[mt][nt][2] * ivhi; hi.y = acc[mt][nt][3] * ivhi;
            *(float2*)(outbase + (size_t)row0 * kDV + col)       = lo;
            *(float2*)(outbase + (size_t)(row0 + 8) * kDV + col) = hi;
        }
    }

    // ---- attn rescale: each thread rescales exactly the float4s it wrote ----
    #pragma unroll
    for (int i = 0; i < 2; ++i) {
        float* aprow = attnbase + (size_t)(rp * 2 + i) * kL + cg * 4;
        const float iv = invr[i];
        #pragma unroll 4
        for (int jt = 0; jt < NTILES; ++jt) {
            float4 e = *(const float4*)(aprow + jt * KT);
            e.x *= iv; e.y *= iv; e.z *= iv; e.w *= iv;
            *(float4*)(aprow + jt * KT) = e;
        }
    }
}

} // namespace

extern "C" void kernel_launch(void* const* d_in, const int* in_sizes, int n_in,
                              void* d_out, int out_size) {
    const float* v    = (const float*)d_in[0];
    const float* a1   = (const float*)d_in[1];
    const float* a2   = (const float*)d_in[2];
    const int*   mask = (const int*)d_in[3];

    float* out  = (float*)d_out;
    float* attn = out + (size_t)kB * kH * kL * kDV;

    const int smem = (int)sizeof(SmemLayout);
    cudaFuncSetAttribute(fra_kernel, cudaFuncAttributeMaxDynamicSharedMemorySize, smem);

    dim3 grid(kH, kL / TM, kB);   // heads fastest -> mask tile L2 reuse across 8 heads
    fra_kernel<<<grid, NT, smem>>>(v, a1, a2, mask, out, attn);
}

// round 9
// speedup vs baseline: 2.1288x; 1.0111x over previous
#include <cuda_runtime.h>
#include <cstdint>
#include <cstddef>

namespace {

constexpr int kB  = 4;
constexpr int kH  = 8;
constexpr int kL  = 2048;
constexpr int kR  = 8;
constexpr int kDV = 128;

constexpr int TM = 64;           // rows per CTA
constexpr int KT = 32;           // K-tile
constexpr int NT = 256;          // threads
constexpr int NTILES = kL / KT;  // 64

constexpr int PSTRIDE = 36;      // p row stride (u32): A-frag conflict-free
constexpr int VSTRIDE = 136;     // v row stride (u32): B-frag conflict-free
constexpr float kLog2e = 1.44269504088896340736f;

typedef unsigned long long ull;

__device__ __forceinline__ ull dup2(float x) {
    ull r; asm("mov.b64 %0, {%1,%1};" : "=l"(r) : "f"(x)); return r;
}
__device__ __forceinline__ void unpack2(ull v, float& lo, float& hi) {
    asm("mov.b64 {%0,%1}, %2;" : "=f"(lo), "=f"(hi) : "l"(v));
}
__device__ __forceinline__ ull fma2(ull a, ull b, ull c) {
    ull d; asm("fma.rn.f32x2 %0, %1, %2, %3;" : "=l"(d) : "l"(a), "l"(b), "l"(c));
    return d;
}
__device__ __forceinline__ uint32_t f2tf32(float x) {
    uint32_t r; asm("cvt.rna.tf32.f32 %0, %1;" : "=r"(r) : "f"(x)); return r;
}
__device__ __forceinline__ float ex2(float x) {
    float r; asm("ex2.approx.f32 %0, %1;" : "=f"(r) : "f"(x)); return r;
}
__device__ __forceinline__ void mma_tf32(float d[4], const uint32_t a[4],
                                         uint32_t b0, uint32_t b1) {
    asm volatile(
        "mma.sync.aligned.m16n8k8.row.col.f32.tf32.tf32.f32 "
        "{%0,%1,%2,%3}, {%4,%5,%6,%7}, {%8,%9}, {%0,%1,%2,%3};"
        : "+f"(d[0]), "+f"(d[1]), "+f"(d[2]), "+f"(d[3])
        : "r"(a[0]), "r"(a[1]), "r"(a[2]), "r"(a[3]), "r"(b0), "r"(b1));
}
__device__ __forceinline__ uint32_t smem_u32(const void* p) {
    uint32_t a;
    asm("{ .reg .u64 t; cvta.to.shared.u64 t, %1; cvt.u32.u64 %0, t; }"
        : "=r"(a) : "l"(p));
    return a;
}
__device__ __forceinline__ void cp16(uint32_t saddr, const void* g) {
    asm volatile("cp.async.ca.shared.global [%0], [%1], 16;"
                 :: "r"(saddr), "l"(g) : "memory");
}
__device__ __forceinline__ void cp_commit() {
    asm volatile("cp.async.commit_group;" ::: "memory");
}
__device__ __forceinline__ void cp_wait1() {
    asm volatile("cp.async.wait_group 1;" ::: "memory");
}

struct __align__(16) SmemLayout {
    uint32_t p[2][TM][PSTRIDE];    // 18.4 KB (tf32 E tiles, double buffered)
    uint32_t v[3][KT][VSTRIDE];    // 52.2 KB (raw f32 v tiles, cp.async ring)
    float    a2t[2][kR][KT];       // 2 KB   (streamed a2 K-tiles)
    float    inv[TM];              // 256 B
};
// ~73 KB -> 2 CTAs/SM

__global__ void __launch_bounds__(NT, 2)
fra_kernel(const float* __restrict__ gv,
           const float* __restrict__ ga1,
           const float* __restrict__ ga2,
           const int*   __restrict__ gmask,
           float* __restrict__ gout,
           float* __restrict__ gattn)
{
    extern __shared__ char smem_raw[];
    SmemLayout& S = *reinterpret_cast<SmemLayout*>(smem_raw);

    const int h    = blockIdx.x;   // heads fastest: 8 heads share mask tile in L2
    const int tile = blockIdx.y;
    const int b    = blockIdx.z;
    const int bh   = b * kH + h;
    const int i0g  = tile * TM;
    const int t    = threadIdx.x;
    const int w    = t >> 5;
    const int l    = t & 31;

    const float* a2base = ga2 + (size_t)bh * kR * kL;
    const float* a1base = ga1 + ((size_t)bh * kL + i0g) * kR;
    const float* vbase  = gv  + (size_t)bh * kL * kDV;
    const int*   mbase  = gmask + ((size_t)b * kL + i0g) * kL;
    float* attnbase = gattn + ((size_t)bh * kL + i0g) * kL;
    float* outbase  = gout  + ((size_t)bh * kL + i0g) * kDV;

    // score mapping: rows 2*rp+i (i=0,1), cols cg*4 within K-tile
    const int rp = t >> 3;   // 0..31
    const int cg = t & 7;    // 0..7

    // a1 (pre-scaled by log2e for ex2) for this thread's 2 rows
    float a1r[2][kR];
    #pragma unroll
    for (int i = 0; i < 2; ++i) {
        const float4* src = (const float4*)(a1base + (size_t)(rp * 2 + i) * kR);
        float4 q0 = src[0], q1 = src[1];
        a1r[i][0] = q0.x * kLog2e; a1r[i][1] = q0.y * kLog2e;
        a1r[i][2] = q0.z * kLog2e; a1r[i][3] = q0.w * kLog2e;
        a1r[i][4] = q1.x * kLog2e; a1r[i][5] = q1.y * kLog2e;
        a1r[i][6] = q1.z * kLog2e; a1r[i][7] = q1.w * kLog2e;
    }

    // GEMM warp grid 2x4 (wm x wn); warp tile 32 rows x 32 cols
    const int wm  = w >> 2;
    const int wn  = w & 3;
    const int qid = l >> 2;
    const int tig = l & 3;

    float acc[2][4][4];
    #pragma unroll
    for (int mt = 0; mt < 2; ++mt)
        #pragma unroll
        for (int nt = 0; nt < 4; ++nt)
            #pragma unroll
            for (int e = 0; e < 4; ++e) acc[mt][nt][e] = 0.f;

    float rs[2] = {0.f, 0.f};

    // ---- cp.async v addressing ----
    const uint32_t vs_base = smem_u32(&S.v[0][0][0]);
    uint32_t voff[4];
    #pragma unroll
    for (int k = 0; k < 4; ++k)
        voff[k] = (uint32_t)(((w + 8 * k) * VSTRIDE + 4 * l) * 4);
    const float* vg[4];
    #pragma unroll
    for (int k = 0; k < 4; ++k)
        vg[k] = vbase + (size_t)(w + 8 * k) * kDV + 4 * l;
    constexpr uint32_t VSLOT = KT * VSTRIDE * 4;   // bytes per slot
    constexpr size_t   VGT   = (size_t)KT * kDV;   // global floats per tile

    // ---- prologue ----
    // v tile 0 -> slot 0
    #pragma unroll
    for (int k = 0; k < 4; ++k) cp16(vs_base + voff[k], vg[k]);
    cp_commit();

    // a2 tile 0
    const int ar = t >> 3;
    const int ac = t & 7;
    if (t < 64)
        *(float4*)&S.a2t[0][ar][ac * 4] =
            *(const float4*)(a2base + (size_t)ar * kL + ac * 4);

    // mask tiles 0,1 preloaded (parity buffer)
    int4 mq_buf[2][2];
    #pragma unroll
    for (int i = 0; i < 2; ++i) {
        mq_buf[0][i] = *(const int4*)(mbase + (size_t)(rp * 2 + i) * kL + 0 * KT + cg * 4);
        mq_buf[1][i] = *(const int4*)(mbase + (size_t)(rp * 2 + i) * kL + 1 * KT + cg * 4);
    }
    __syncthreads();

    // ================= fused sweep: e = mask*exp(s); attn STG; E@V MMA =================
    int vcur = 0, vnxt = 1;
    #pragma unroll 2
    for (int jt = 0; jt < NTILES; ++jt) {
        const int buf = jt & 1;
        const int j0  = jt * KT;

        // ---- issue cp.async for v tile jt+1 into slot vnxt ----
        {
            const size_t goff = (jt + 1 < NTILES) ? (size_t)(jt + 1) * VGT : 0;
            const uint32_t sb = vs_base + (uint32_t)vnxt * VSLOT;
            #pragma unroll
            for (int k = 0; k < 4; ++k) cp16(sb + voff[k], vg[k] + goff);
            cp_commit();
        }

        // ---- prefetch next a2 tile ----
        float4 a2n;
        const int jn = (jt + 1 < NTILES) ? j0 + KT : 0;
        if (t < 64)
            a2n = *(const float4*)(a2base + (size_t)ar * kL + jn + ac * 4);

        // ---- scores: 2 rows x 4 cols (f32x2) from smem a2 tile ----
        ull sac[2][2];
        sac[0][0] = 0ULL; sac[0][1] = 0ULL;
        sac[1][0] = 0ULL; sac[1][1] = 0ULL;
        #pragma unroll
        for (int r = 0; r < kR; ++r) {
            ulonglong2 q = *(const ulonglong2*)&S.a2t[buf][r][cg * 4];
            #pragma unroll
            for (int i = 0; i < 2; ++i) {
                ull ad = dup2(a1r[i][r]);
                sac[i][0] = fma2(ad, q.x, sac[i][0]);
                sac[i][1] = fma2(ad, q.y, sac[i][1]);
            }
        }

        // ---- e = mask*exp2(s~): attn STG (unnormalized), rowsum, p STS (tf32) ----
        #pragma unroll
        for (int i = 0; i < 2; ++i) {
            const int row = rp * 2 + i;
            const int4 m = mq_buf[buf][i];
            float e0, e1, e2, e3;
            unpack2(sac[i][0], e0, e1);
            unpack2(sac[i][1], e2, e3);
            float4 e;
            e.x = m.x ? ex2(e0) : 0.f;
            e.y = m.y ? ex2(e1) : 0.f;
            e.z = m.z ? ex2(e2) : 0.f;
            e.w = m.w ? ex2(e3) : 0.f;
            rs[i] += (e.x + e.y) + (e.z + e.w);
            *(float4*)(attnbase + (size_t)row * kL + j0 + cg * 4) = e;
            uint4 u;
            u.x = f2tf32(e.x); u.y = f2tf32(e.y);
            u.z = f2tf32(e.z); u.w = f2tf32(e.w);
            *(uint4*)&S.p[buf][row][cg * 4] = u;
        }

        // ---- mask prefetch 2 tiles ahead (into the parity slot just consumed) ----
        {
            const int jm = (jt + 2 < NTILES) ? (jt + 2) * KT : 0;
            #pragma unroll
            for (int i = 0; i < 2; ++i)
                mq_buf[buf][i] =
                    *(const int4*)(mbase + (size_t)(rp * 2 + i) * kL + jm + cg * 4);
        }

        // ---- stage next a2 tile into the other buffer ----
        if (t < 64)
            *(float4*)&S.a2t[buf ^ 1][ar][ac * 4] = a2n;

        cp_wait1();        // v tile jt resident (group jt done; group jt+1 may fly)
        __syncthreads();   // publish p/a2/v(jt)

        // ---- HMMA: D[32*wm.., 32*wn..] += E * V  (V raw f32 -> tf32 truncation) ----
        const uint32_t* vt = &S.v[vcur][0][0];
        #pragma unroll
        for (int s = 0; s < 4; ++s) {
            const int k0 = 8 * s + tig;
            uint32_t a[2][4];
            #pragma unroll
            for (int mt = 0; mt < 2; ++mt) {
                const uint32_t* pr = &S.p[buf][32 * wm + 16 * mt][0];
                a[mt][0] = pr[(size_t)qid * PSTRIDE + k0];
                a[mt][1] = pr[(size_t)(qid + 8) * PSTRIDE + k0];
                a[mt][2] = pr[(size_t)qid * PSTRIDE + k0 + 4];
                a[mt][3] = pr[(size_t)(qid + 8) * PSTRIDE + k0 + 4];
            }
            #pragma unroll
            for (int nt = 0; nt < 4; ++nt) {
                const int n = 32 * wn + 8 * nt + qid;
                uint32_t b0 = vt[(size_t)(8 * s + tig) * VSTRIDE + n];
                uint32_t b1 = vt[(size_t)(8 * s + 4 + tig) * VSTRIDE + n];
                mma_tf32(acc[0][nt], a[0], b0, b1);
                mma_tf32(acc[1][nt], a[1], b0, b1);
            }
        }

        vcur = vnxt;
        vnxt = (vnxt == 2) ? 0 : vnxt + 1;
    }

    // ---- rowsum reduce over 8 cg lanes (warp-local) ----
    float invr[2];
    #pragma unroll
    for (int i = 0; i < 2; ++i) {
        float r = rs[i];
        r += __shfl_xor_sync(0xffffffffu, r, 1);
        r += __shfl_xor_sync(0xffffffffu, r, 2);
        r += __shfl_xor_sync(0xffffffffu, r, 4);
        invr[i] = 1.0f / r;
        if (cg == 0) S.inv[rp * 2 + i] = invr[i];
    }
    __syncthreads();

    // ---- out epilogue: scale accumulators by row inv ----
    #pragma unroll
    for (int mt = 0; mt < 2; ++mt) {
        const int row0 = 32 * wm + 16 * mt + qid;
        const float ivlo = S.inv[row0];
        const float ivhi = S.inv[row0 + 8];
        #pragma unroll
        for (int nt = 0; nt < 4; ++nt) {
            const int col = 32 * wn + 8 * nt + 2 * tig;
            float2 lo; lo.x = acc[mt][nt][0] * ivlo; lo.y = acc[mt][nt][1] * ivlo;
            float2 hi; hi.x = acc[mt][nt][2] * ivhi; hi.y = acc[mt][nt][3] * ivhi;
            *(float2*)(outbase + (size_t)row0 * kDV + col)       = lo;
            *(float2*)(outbase + (size_t)(row0 + 8) * kDV + col) = hi;
        }
    }

    // ---- attn rescale: each thread rescales exactly the float4s it wrote ----
    #pragma unroll
    for (int i = 0; i < 2; ++i) {
        float* aprow = attnbase + (size_t)(rp * 2 + i) * kL + cg * 4;
        const float iv = invr[i];
        #pragma unroll 4
        for (int jt = 0; jt < NTILES; ++jt) {
            float4 e = *(const float4*)(aprow + jt * KT);
            e.x *= iv; e.y *= iv; e.z *= iv; e.w *= iv;
            *(float4*)(aprow + jt * KT) = e;
        }
    }
}

} // namespace

extern "C" void kernel_launch(void* const* d_in, const int* in_sizes, int n_in,
                              void* d_out, int out_size) {
    const float* v    = (const float*)d_in[0];
    const float* a1   = (const float*)d_in[1];
    const float* a2   = (const float*)d_in[2];
    const int*   mask = (const int*)d_in[3];

    float* out  = (float*)d_out;
    float* attn = out + (size_t)kB * kH * kL * kDV;

    const int smem = (int)sizeof(SmemLayout);
    cudaFuncSetAttribute(fra_kernel, cudaFuncAttributeMaxDynamicSharedMemorySize, smem);

    dim3 grid(kH, kL / TM, kB);   // heads fastest -> mask tile L2 reuse across 8 heads
    fra_kernel<<<grid, NT, smem>>>(v, a1, a2, mask, out, attn);
}